// round 5
// baseline (speedup 1.0000x reference)
#include <cuda_runtime.h>
#include <cuda_bf16.h>
#include <cstdint>

// Problem constants (fixed shapes)
#define B_    96
#define N1    196      // image tokens
#define N2    77       // text tokens
#define DIM   512
#define MPAD  224      // N1 padded to 14 * 16
#define NPAD  80       // N2 padded to 10 * 8
#define NKSTEP 32      // 512 / 16
#define NWARP 7
#define NTHREADS 224

// Preconverted bf16 inputs (padded) + logit matrices as device globals (no runtime alloc)
__device__ __nv_bfloat16 g_img[(size_t)B_ * MPAD * DIM];   // 22 MB
__device__ __nv_bfloat16 g_txt[(size_t)B_ * NPAD * DIM];   // 7.9 MB
__device__ float g_i2t[B_ * B_];
__device__ float g_t2i[B_ * B_];

// ---------------------------------------------------------------------------
// Conversion kernels: fp32 -> bf16, pad extra rows with zeros
// ---------------------------------------------------------------------------
__global__ void conv_img_kernel(const float* __restrict__ in) {
    int idx = blockIdx.x * blockDim.x + threadIdx.x;      // pair index
    const int TOT = B_ * MPAD * (DIM / 2);
    if (idx >= TOT) return;
    int k2 = idx & (DIM / 2 - 1);
    int rm = idx >> 8;                                    // b*MPAD + m
    int m = rm % MPAD, b = rm / MPAD;
    float2 v = make_float2(0.f, 0.f);
    if (m < N1) v = reinterpret_cast<const float2*>(in)[((size_t)b * N1 + m) * (DIM / 2) + k2];
    __nv_bfloat162 o = __floats2bfloat162_rn(v.x, v.y);
    reinterpret_cast<__nv_bfloat162*>(g_img)[idx] = o;
}

__global__ void conv_txt_kernel(const float* __restrict__ in) {
    int idx = blockIdx.x * blockDim.x + threadIdx.x;
    const int TOT = B_ * NPAD * (DIM / 2);
    if (idx >= TOT) return;
    int k2 = idx & (DIM / 2 - 1);
    int rm = idx >> 8;                                    // b*NPAD + r
    int r = rm % NPAD, b = rm / NPAD;
    float2 v = make_float2(0.f, 0.f);
    if (r < N2) v = reinterpret_cast<const float2*>(in)[((size_t)b * N2 + r) * (DIM / 2) + k2];
    __nv_bfloat162 o = __floats2bfloat162_rn(v.x, v.y);
    reinterpret_cast<__nv_bfloat162*>(g_txt)[idx] = o;
}

// ---------------------------------------------------------------------------
// Main kernel: one CTA per (bi, bt), 196x77x512 GEMM + fused max/mean epilogue
// ---------------------------------------------------------------------------
// smem stage layout: rows of 16 halfs (one k16 chunk) padded to 24 halfs (48B)
// Bank pattern for fragment loads: word addr = row*12 + t (+4) -> conflict-free.
#define ROWH 24   // halfs per smem row (16 data + 8 pad)
#define ROWU 12   // uint32 per smem row

__device__ __forceinline__ void cp16(void* dst, const void* src) {
    uint32_t d = (uint32_t)__cvta_generic_to_shared(dst);
    asm volatile("cp.async.cg.shared.global [%0], [%1], 16;\n" :: "r"(d), "l"(src));
}
__device__ __forceinline__ void cp_commit() {
    asm volatile("cp.async.commit_group;\n");
}
template <int N>
__device__ __forceinline__ void cp_wait() {
    asm volatile("cp.async.wait_group %0;\n" :: "n"(N));
}

__device__ __forceinline__ void mma16816(float& d0, float& d1, float& d2, float& d3,
                                         uint32_t a0, uint32_t a1, uint32_t a2, uint32_t a3,
                                         uint32_t b0, uint32_t b1) {
    asm volatile(
        "mma.sync.aligned.m16n8k16.row.col.f32.bf16.bf16.f32 "
        "{%0,%1,%2,%3}, {%4,%5,%6,%7}, {%8,%9}, {%0,%1,%2,%3};\n"
        : "+f"(d0), "+f"(d1), "+f"(d2), "+f"(d3)
        : "r"(a0), "r"(a1), "r"(a2), "r"(a3), "r"(b0), "r"(b1));
}

__global__ void __launch_bounds__(NTHREADS, 2) gemm_pair_kernel() {
    __shared__ __align__(16) __nv_bfloat16 sA[3][MPAD * ROWH];  // 3 * 10752 B
    __shared__ __align__(16) __nv_bfloat16 sB[3][NPAD * ROWH];  // 3 * 3840 B
    __shared__ float s_cmax[NWARP][NPAD];
    __shared__ float s_rowsum[NWARP];

    const int bt = blockIdx.x;
    const int bi = blockIdx.y;
    const int tid = threadIdx.x;
    const int lane = tid & 31;
    const int w = tid >> 5;
    const int g = lane >> 2;   // group (row within 8)
    const int t = lane & 3;    // thread-in-group

    const __nv_bfloat16* __restrict__ Ag = g_img + (size_t)bi * MPAD * DIM;
    const __nv_bfloat16* __restrict__ Bg = g_txt + (size_t)bt * NPAD * DIM;

    float acc[2][10][4];
#pragma unroll
    for (int mi = 0; mi < 2; mi++)
#pragma unroll
        for (int nt = 0; nt < 10; nt++)
#pragma unroll
            for (int j = 0; j < 4; j++) acc[mi][nt][j] = 0.f;

    // ---- stage loader: 448 A chunks + 160 B chunks of 16B each ----
    auto load_stage = [&](int buf, int ks) {
        const int k0 = ks * 16;
        for (int i = tid; i < 608; i += NTHREADS) {
            if (i < 448) {
                int row = i >> 1, sub = i & 1;
                cp16(&sA[buf][row * ROWH + sub * 8], Ag + (size_t)row * DIM + k0 + sub * 8);
            } else {
                int j = i - 448;
                int row = j >> 1, sub = j & 1;
                cp16(&sB[buf][row * ROWH + sub * 8], Bg + (size_t)row * DIM + k0 + sub * 8);
            }
        }
        cp_commit();
    };

    // ---- 3-deep pipeline over 32 k16 stages ----
    load_stage(0, 0);
    load_stage(1, 1);

    int buf = 0;
    for (int ks = 0; ks < NKSTEP; ks++) {
        if (ks + 2 < NKSTEP) {
            int nb = buf + 2; if (nb >= 3) nb -= 3;
            load_stage(nb, ks + 2);
            cp_wait<2>();
        } else if (ks + 1 < NKSTEP) {
            cp_wait<1>();
        } else {
            cp_wait<0>();
        }
        __syncthreads();

        const uint32_t* Ap = reinterpret_cast<const uint32_t*>(sA[buf]);
        const uint32_t* Bp = reinterpret_cast<const uint32_t*>(sB[buf]);

        uint32_t a[2][4];
#pragma unroll
        for (int mi = 0; mi < 2; mi++) {
            int base = (w * 2 + mi) * 16;
            a[mi][0] = Ap[(base + g) * ROWU + t];
            a[mi][1] = Ap[(base + g + 8) * ROWU + t];
            a[mi][2] = Ap[(base + g) * ROWU + t + 4];
            a[mi][3] = Ap[(base + g + 8) * ROWU + t + 4];
        }
#pragma unroll
        for (int nt = 0; nt < 10; nt++) {
            uint32_t b0 = Bp[(nt * 8 + g) * ROWU + t];
            uint32_t b1 = Bp[(nt * 8 + g) * ROWU + t + 4];
#pragma unroll
            for (int mi = 0; mi < 2; mi++) {
                mma16816(acc[mi][nt][0], acc[mi][nt][1], acc[mi][nt][2], acc[mi][nt][3],
                         a[mi][0], a[mi][1], a[mi][2], a[mi][3], b0, b1);
            }
        }
        __syncthreads();   // before buf gets overwritten by a later load
        buf++; if (buf >= 3) buf -= 3;
    }

    // ---------------- epilogue: fused row-max/mean and col-max/mean ----------
    const float NEG = -3.0e38f;

    // (1) rowmax over n (< N2), then mean over valid rows -> i2t[bi,bt]
    float rowsum = 0.f;
#pragma unroll
    for (int mi = 0; mi < 2; mi++) {
        int base = (w * 2 + mi) * 16;
        float mx_lo = NEG, mx_hi = NEG;
#pragma unroll
        for (int nt = 0; nt < 10; nt++) {
#pragma unroll
            for (int j = 0; j < 2; j++) {
                int n = nt * 8 + 2 * t + j;
                if (n < N2) {
                    mx_lo = fmaxf(mx_lo, acc[mi][nt][j]);
                    mx_hi = fmaxf(mx_hi, acc[mi][nt][2 + j]);
                }
            }
        }
        // reduce over the 4 lanes sharing a row (t dimension)
        mx_lo = fmaxf(mx_lo, __shfl_xor_sync(0xffffffffu, mx_lo, 1));
        mx_lo = fmaxf(mx_lo, __shfl_xor_sync(0xffffffffu, mx_lo, 2));
        mx_hi = fmaxf(mx_hi, __shfl_xor_sync(0xffffffffu, mx_hi, 1));
        mx_hi = fmaxf(mx_hi, __shfl_xor_sync(0xffffffffu, mx_hi, 2));
        int r_lo = base + g, r_hi = base + g + 8;
        if (t == 0) {
            if (r_lo < N1) rowsum += mx_lo;
            if (r_hi < N1) rowsum += mx_hi;
        }
    }
    // warp-sum (only t==0 lanes contributed)
    rowsum += __shfl_xor_sync(0xffffffffu, rowsum, 16);
    rowsum += __shfl_xor_sync(0xffffffffu, rowsum, 8);
    rowsum += __shfl_xor_sync(0xffffffffu, rowsum, 4);
    rowsum += __shfl_xor_sync(0xffffffffu, rowsum, 2);
    rowsum += __shfl_xor_sync(0xffffffffu, rowsum, 1);
    if (lane == 0) s_rowsum[w] = rowsum;

    // (2) colmax over this warp's valid rows, staged to smem per-warp
#pragma unroll
    for (int nt = 0; nt < 10; nt++) {
#pragma unroll
        for (int j = 0; j < 2; j++) {
            float cm = NEG;
#pragma unroll
            for (int mi = 0; mi < 2; mi++) {
                int base = (w * 2 + mi) * 16;
                if (base + g < N1)     cm = fmaxf(cm, acc[mi][nt][j]);
                if (base + g + 8 < N1) cm = fmaxf(cm, acc[mi][nt][2 + j]);
            }
            // reduce over the 8 groups (g dimension)
            cm = fmaxf(cm, __shfl_xor_sync(0xffffffffu, cm, 4));
            cm = fmaxf(cm, __shfl_xor_sync(0xffffffffu, cm, 8));
            cm = fmaxf(cm, __shfl_xor_sync(0xffffffffu, cm, 16));
            if (g == 0) s_cmax[w][nt * 8 + 2 * t + j] = cm;
        }
    }
    __syncthreads();

    // cross-warp colmax
    if (tid < NPAD) {
        float m = s_cmax[0][tid];
#pragma unroll
        for (int w2 = 1; w2 < NWARP; w2++) m = fmaxf(m, s_cmax[w2][tid]);
        s_cmax[0][tid] = m;
    }
    __syncthreads();

    if (tid == 0) {
        float rs = 0.f;
#pragma unroll
        for (int w2 = 0; w2 < NWARP; w2++) rs += s_rowsum[w2];
        g_i2t[bi * B_ + bt] = rs * (1.0f / N1);
        float cs = 0.f;
        for (int n = 0; n < N2; n++) cs += s_cmax[0][n];
        g_t2i[bt * B_ + bi] = cs * (1.0f / N2);
    }
}

// ---------------------------------------------------------------------------
// Final cross-entropy: labels = arange, mean; loss = 0.5 * (ce(i2t) + ce(t2i))
// ---------------------------------------------------------------------------
__global__ void ce_kernel(float* __restrict__ out) {
    __shared__ float sred[128];
    int b = threadIdx.x;
    float v = 0.f;
    if (b < B_) {
        float mx1 = -3.0e38f, mx2 = -3.0e38f;
        for (int c = 0; c < B_; c++) {
            mx1 = fmaxf(mx1, g_i2t[b * B_ + c]);
            mx2 = fmaxf(mx2, g_t2i[b * B_ + c]);
        }
        float s1 = 0.f, s2 = 0.f;
        for (int c = 0; c < B_; c++) {
            s1 += expf(g_i2t[b * B_ + c] - mx1);
            s2 += expf(g_t2i[b * B_ + c] - mx2);
        }
        v = (mx1 + logf(s1) - g_i2t[b * B_ + b]) +
            (mx2 + logf(s2) - g_t2i[b * B_ + b]);
    }
    sred[b] = v;
    __syncthreads();
    for (int off = 64; off > 0; off >>= 1) {
        if (b < off) sred[b] += sred[b + off];
        __syncthreads();
    }
    if (b == 0) out[0] = 0.5f * sred[0] * (1.0f / B_);
}

// ---------------------------------------------------------------------------
extern "C" void kernel_launch(void* const* d_in, const int* in_sizes, int n_in,
                              void* d_out, int out_size) {
    const float* img = (const float*)d_in[0];   // [96, 196, 512] fp32
    const float* txt = (const float*)d_in[1];   // [96, 77, 512] fp32
    float* out = (float*)d_out;

    {
        int tot = B_ * MPAD * (DIM / 2);
        conv_img_kernel<<<(tot + 255) / 256, 256>>>(img);
    }
    {
        int tot = B_ * NPAD * (DIM / 2);
        conv_txt_kernel<<<(tot + 255) / 256, 256>>>(txt);
    }
    gemm_pair_kernel<<<dim3(B_, B_), NTHREADS>>>();
    ce_kernel<<<1, 128>>>(out);
}

// round 11
// speedup vs baseline: 1.1982x; 1.1982x over previous
#include <cuda_runtime.h>
#include <cuda_bf16.h>
#include <cstdint>

// ---------------------------------------------------------------------------
// Problem constants (fixed shapes)
// ---------------------------------------------------------------------------
#define B_    96
#define N1    196      // image tokens (valid rows)
#define N2    77       // text tokens (valid cols)
#define DIM   512
#define MPAD  224      // image rows padded to 14 x 16 (zeros beyond 196)
#define NPAD  80       // text rows padded to 10 x 8 (zeros beyond 77)
#define Gg    2        // text blocks per CTA
#define KC    64       // K elements per pipeline stage
#define KSTEPS 8       // 512 / 64
#define NSTAGES 3
#define NWARP 14
#define NTHREADS 448

// smem stage layout: rows of 128B data padded to 144B stride.
// 144B stride = word-stride 36 == 4 (mod 32) -> 8-row ldmatrix groups hit all
// 32 banks exactly once: conflict-free LDSM and conflict-free cp.async stores.
#define ROWB      144
#define A_ROWS    224
#define B_ROWS    160                      // Gg * 80
#define A_BYTES   (A_ROWS * ROWB)          // 32256
#define B_REGION  A_BYTES
#define STAGE_BYTES (A_BYTES + B_ROWS * ROWB)   // 55296
#define CHUNKS    ((A_ROWS + B_ROWS) * 8)  // 3072 x 16B per stage

#define SMEM_COL  (NSTAGES * STAGE_BYTES)        // float[14][80]
#define SMEM_RS   (SMEM_COL + NWARP * NPAD * 4)  // float[14]
#define SMEM_TOTAL (SMEM_RS + NWARP * 4)

// Preconverted bf16 inputs (padded) + logit matrices as device globals
__device__ __nv_bfloat16 g_img[(size_t)B_ * MPAD * DIM];   // 22 MB
__device__ __nv_bfloat16 g_txt[(size_t)B_ * NPAD * DIM];   // 7.9 MB
__device__ float g_i2t[B_ * B_];
__device__ float g_t2i[B_ * B_];

// ---------------------------------------------------------------------------
// PTX helpers (plain sm_103 feature set only: cp.async, ldmatrix, mma.sync)
// ---------------------------------------------------------------------------
__device__ __forceinline__ void cp16(uint32_t dst_smem, const void* src) {
    asm volatile("cp.async.cg.shared.global [%0], [%1], 16;\n" :: "r"(dst_smem), "l"(src));
}
__device__ __forceinline__ void cp_commit() {
    asm volatile("cp.async.commit_group;\n");
}
template <int N>
__device__ __forceinline__ void cp_wait() {
    asm volatile("cp.async.wait_group %0;\n" :: "n"(N));
}

__device__ __forceinline__ void ldsm4(uint32_t& r0, uint32_t& r1, uint32_t& r2, uint32_t& r3,
                                      uint32_t addr) {
    asm volatile("ldmatrix.sync.aligned.m8n8.x4.shared.b16 {%0,%1,%2,%3}, [%4];\n"
                 : "=r"(r0), "=r"(r1), "=r"(r2), "=r"(r3) : "r"(addr));
}

__device__ __forceinline__ void mma16816(float* d,
                                         uint32_t a0, uint32_t a1, uint32_t a2, uint32_t a3,
                                         uint32_t b0, uint32_t b1) {
    asm volatile(
        "mma.sync.aligned.m16n8k16.row.col.f32.bf16.bf16.f32 "
        "{%0,%1,%2,%3}, {%4,%5,%6,%7}, {%8,%9}, {%0,%1,%2,%3};\n"
        : "+f"(d[0]), "+f"(d[1]), "+f"(d[2]), "+f"(d[3])
        : "r"(a0), "r"(a1), "r"(a2), "r"(a3), "r"(b0), "r"(b1));
}

// ---------------------------------------------------------------------------
// Conversion kernels: fp32 -> bf16, zero-pad extra rows
// ---------------------------------------------------------------------------
__global__ void conv_img_kernel(const float* __restrict__ in) {
    int idx = blockIdx.x * blockDim.x + threadIdx.x;    // bf16x2 pair index
    const int TOT = B_ * MPAD * (DIM / 2);
    if (idx >= TOT) return;
    int k2 = idx & (DIM / 2 - 1);
    int rm = idx >> 8;
    int m = rm % MPAD, b = rm / MPAD;
    float2 v = make_float2(0.f, 0.f);
    if (m < N1) v = reinterpret_cast<const float2*>(in)[((size_t)b * N1 + m) * (DIM / 2) + k2];
    reinterpret_cast<__nv_bfloat162*>(g_img)[idx] = __floats2bfloat162_rn(v.x, v.y);
}

__global__ void conv_txt_kernel(const float* __restrict__ in) {
    int idx = blockIdx.x * blockDim.x + threadIdx.x;
    const int TOT = B_ * NPAD * (DIM / 2);
    if (idx >= TOT) return;
    int k2 = idx & (DIM / 2 - 1);
    int rm = idx >> 8;
    int r = rm % NPAD, b = rm / NPAD;
    float2 v = make_float2(0.f, 0.f);
    if (r < N2) v = reinterpret_cast<const float2*>(in)[((size_t)b * N2 + r) * (DIM / 2) + k2];
    reinterpret_cast<__nv_bfloat162*>(g_txt)[idx] = __floats2bfloat162_rn(v.x, v.y);
}

// ---------------------------------------------------------------------------
// Main kernel: one CTA per (bi, 2 bt blocks). 224x(2x80)x512 bf16 mma.sync
// GEMM with ldmatrix fragment loads, 3-stage cp.async pipeline, fused
// max/mean epilogue. Grid: (48, 96), 448 threads.
// ---------------------------------------------------------------------------
__global__ void __launch_bounds__(NTHREADS, 1) gemm_pair_kernel() {
    extern __shared__ __align__(128) char smem[];
    const uint32_t sb = (uint32_t)__cvta_generic_to_shared(smem);
    const int tid = threadIdx.x;
    const int w = tid >> 5;
    const int lane = tid & 31;
    const int bt0 = blockIdx.x * Gg;
    const int bi = blockIdx.y;

    const __nv_bfloat16* __restrict__ Ag = g_img + (size_t)bi * MPAD * DIM;
    const __nv_bfloat16* __restrict__ Bg = g_txt + (size_t)bt0 * NPAD * DIM;  // 160 rows

    float acc[Gg][10][4];
#pragma unroll
    for (int gb = 0; gb < Gg; gb++)
#pragma unroll
        for (int nt = 0; nt < 10; nt++)
#pragma unroll
            for (int j = 0; j < 4; j++) acc[gb][nt][j] = 0.f;

    // ldmatrix lane-address offsets (within a stage)
    // A (m16 x k16 tile of warp w): lanes 0-15 rows m0..15 @ +0, lanes 16-31 same rows @ +16B
    const uint32_t a_off = (uint32_t)(w * 16 + (lane & 15)) * ROWB + ((lane >> 4) << 4);
    // B (two n8 tiles per x4): lanes 0-7 tile j rows @+0, 8-15 tile j @+16B,
    //                          16-23 tile j+1 @+0, 24-31 tile j+1 @+16B
    const uint32_t b_off = (uint32_t)(((lane >> 4) << 3) + (lane & 7)) * ROWB
                           + (((lane >> 3) & 1) << 4);

    // stage loader: 3072 16B chunks (A rows 0-223, B rows 0-159)
    auto load_stage = [&](int s) {
        const int k0 = s * KC;
        const uint32_t base = sb + (s % NSTAGES) * STAGE_BYTES;
        for (int i = tid; i < CHUNKS; i += NTHREADS) {
            int row = i >> 3, sub = i & 7;
            uint32_t dst;
            const __nv_bfloat16* src;
            if (row < A_ROWS) {
                dst = base + (uint32_t)row * ROWB + (sub << 4);
                src = Ag + (size_t)row * DIM + k0 + sub * 8;
            } else {
                int r = row - A_ROWS;
                dst = base + B_REGION + (uint32_t)r * ROWB + (sub << 4);
                src = Bg + (size_t)r * DIM + k0 + sub * 8;
            }
            cp16(dst, src);
        }
    };

    // prologue
    load_stage(0); cp_commit();
    load_stage(1); cp_commit();

    // ---- mainloop: single barrier per k64 stage ----
    for (int ks = 0; ks < KSTEPS; ks++) {
        cp_wait<1>();            // stage ks resident (groups retire in order)
        __syncthreads();         // also: everyone finished compute(ks-1)
        if (ks + 2 < KSTEPS) load_stage(ks + 2);   // buffer freed at iter ks-1
        cp_commit();

        const uint32_t stg = sb + (ks % NSTAGES) * STAGE_BYTES;
#pragma unroll
        for (int c = 0; c < 4; c++) {              // k16 sub-chunks
            uint32_t a0, a1, a2, a3;
            ldsm4(a0, a1, a2, a3, stg + a_off + c * 32);
#pragma unroll
            for (int gb = 0; gb < Gg; gb++) {
                const uint32_t bbase = stg + B_REGION + gb * (80 * ROWB) + b_off + c * 32;
#pragma unroll
                for (int jp = 0; jp < 5; jp++) {   // n-tile pairs
                    uint32_t b0, b1, b2, b3;
                    ldsm4(b0, b1, b2, b3, bbase + jp * (16 * ROWB));
                    mma16816(acc[gb][2 * jp],     a0, a1, a2, a3, b0, b1);
                    mma16816(acc[gb][2 * jp + 1], a0, a1, a2, a3, b2, b3);
                }
            }
        }
    }

    // ---- epilogue: fused rowmax->mean (i2t) and colmax->mean (t2i) ----
    const float NEG = -3.0e38f;
    float* s_col = (float*)(smem + SMEM_COL);   // [14][80]
    float* s_rs = (float*)(smem + SMEM_RS);     // [14]
    const int r0 = w * 16 + (lane >> 2);
    const int r1 = r0 + 8;
    const bool ok0 = r0 < N1, ok1 = r1 < N1;

    __syncthreads();   // mainloop fully done before reusing smem region

    for (int gb = 0; gb < Gg; gb++) {
        // (1) row maxima over valid cols
        float rmax0 = NEG, rmax1 = NEG;
#pragma unroll
        for (int nt = 0; nt < 10; nt++) {
#pragma unroll
            for (int j = 0; j < 2; j++) {
                int n = nt * 8 + 2 * (lane & 3) + j;
                if (n < N2) {
                    rmax0 = fmaxf(rmax0, acc[gb][nt][j]);
                    rmax1 = fmaxf(rmax1, acc[gb][nt][2 + j]);
                }
            }
        }
        rmax0 = fmaxf(rmax0, __shfl_xor_sync(0xffffffffu, rmax0, 1));
        rmax0 = fmaxf(rmax0, __shfl_xor_sync(0xffffffffu, rmax0, 2));
        rmax1 = fmaxf(rmax1, __shfl_xor_sync(0xffffffffu, rmax1, 1));
        rmax1 = fmaxf(rmax1, __shfl_xor_sync(0xffffffffu, rmax1, 2));
        float rpart = 0.f;
        if ((lane & 3) == 0) {
            if (ok0) rpart += rmax0;
            if (ok1) rpart += rmax1;
        }
        rpart += __shfl_xor_sync(0xffffffffu, rpart, 16);
        rpart += __shfl_xor_sync(0xffffffffu, rpart, 8);
        rpart += __shfl_xor_sync(0xffffffffu, rpart, 4);
        rpart += __shfl_xor_sync(0xffffffffu, rpart, 2);
        rpart += __shfl_xor_sync(0xffffffffu, rpart, 1);
        if (lane == 0) s_rs[w] = rpart;

        // (2) column maxima over this warp's 16 rows (validity-masked)
#pragma unroll
        for (int nt = 0; nt < 10; nt++) {
#pragma unroll
            for (int j = 0; j < 2; j++) {
                float v0 = ok0 ? acc[gb][nt][j] : NEG;
                float v1 = ok1 ? acc[gb][nt][2 + j] : NEG;
                float cm = fmaxf(v0, v1);
                cm = fmaxf(cm, __shfl_xor_sync(0xffffffffu, cm, 4));
                cm = fmaxf(cm, __shfl_xor_sync(0xffffffffu, cm, 8));
                cm = fmaxf(cm, __shfl_xor_sync(0xffffffffu, cm, 16));
                if (lane < 4) s_col[w * NPAD + nt * 8 + 2 * lane + j] = cm;
            }
        }
        __syncthreads();

        if (w == 0) {
            float csum = 0.f;
            for (int n = lane; n < N2; n += 32) {
                float m = s_col[n];
#pragma unroll
                for (int w2 = 1; w2 < NWARP; w2++) m = fmaxf(m, s_col[w2 * NPAD + n]);
                csum += m;
            }
            csum += __shfl_xor_sync(0xffffffffu, csum, 16);
            csum += __shfl_xor_sync(0xffffffffu, csum, 8);
            csum += __shfl_xor_sync(0xffffffffu, csum, 4);
            csum += __shfl_xor_sync(0xffffffffu, csum, 2);
            csum += __shfl_xor_sync(0xffffffffu, csum, 1);
            if (lane == 0) {
                float rs = 0.f;
#pragma unroll
                for (int w2 = 0; w2 < NWARP; w2++) rs += s_rs[w2];
                g_i2t[bi * B_ + bt0 + gb] = rs * (1.0f / N1);
                g_t2i[(bt0 + gb) * B_ + bi] = csum * (1.0f / N2);
            }
        }
        __syncthreads();   // s_col/s_rs reuse for next gb
    }
}

// ---------------------------------------------------------------------------
// Final cross-entropy: 32 warps, one row-task per warp (192 tasks total)
// ---------------------------------------------------------------------------
__global__ void ce_kernel(float* __restrict__ out) {
    __shared__ float spart[32];
    int w = threadIdx.x >> 5, lane = threadIdx.x & 31;
    float acc = 0.f;
    for (int task = w; task < 2 * B_; task += 32) {
        const float* rowp = (task < B_) ? (g_i2t + task * B_) : (g_t2i + (task - B_) * B_);
        int b = (task < B_) ? task : task - B_;
        float v0 = rowp[lane], v1 = rowp[lane + 32], v2 = rowp[lane + 64];
        float mx = fmaxf(v0, fmaxf(v1, v2));
        mx = fmaxf(mx, __shfl_xor_sync(0xffffffffu, mx, 16));
        mx = fmaxf(mx, __shfl_xor_sync(0xffffffffu, mx, 8));
        mx = fmaxf(mx, __shfl_xor_sync(0xffffffffu, mx, 4));
        mx = fmaxf(mx, __shfl_xor_sync(0xffffffffu, mx, 2));
        mx = fmaxf(mx, __shfl_xor_sync(0xffffffffu, mx, 1));
        float s = expf(v0 - mx) + expf(v1 - mx) + expf(v2 - mx);
        s += __shfl_xor_sync(0xffffffffu, s, 16);
        s += __shfl_xor_sync(0xffffffffu, s, 8);
        s += __shfl_xor_sync(0xffffffffu, s, 4);
        s += __shfl_xor_sync(0xffffffffu, s, 2);
        s += __shfl_xor_sync(0xffffffffu, s, 1);
        if (lane == 0) acc += mx + logf(s) - rowp[b];
    }
    if (lane == 0) spart[w] = acc;
    __syncthreads();
    if (w == 0) {
        float v = spart[lane];
        v += __shfl_xor_sync(0xffffffffu, v, 16);
        v += __shfl_xor_sync(0xffffffffu, v, 8);
        v += __shfl_xor_sync(0xffffffffu, v, 4);
        v += __shfl_xor_sync(0xffffffffu, v, 2);
        v += __shfl_xor_sync(0xffffffffu, v, 1);
        if (lane == 0) out[0] = 0.5f * v * (1.0f / B_);
    }
}

// ---------------------------------------------------------------------------
extern "C" void kernel_launch(void* const* d_in, const int* in_sizes, int n_in,
                              void* d_out, int out_size) {
    const float* img = (const float*)d_in[0];   // [96, 196, 512] fp32
    const float* txt = (const float*)d_in[1];   // [96, 77, 512] fp32
    float* out = (float*)d_out;

    cudaFuncSetAttribute(gemm_pair_kernel,
                         cudaFuncAttributeMaxDynamicSharedMemorySize, SMEM_TOTAL);

    {
        int tot = B_ * MPAD * (DIM / 2);
        conv_img_kernel<<<(tot + 255) / 256, 256>>>(img);
    }
    {
        int tot = B_ * NPAD * (DIM / 2);
        conv_txt_kernel<<<(tot + 255) / 256, 256>>>(txt);
    }
    gemm_pair_kernel<<<dim3(B_ / Gg, B_), NTHREADS, SMEM_TOTAL>>>();
    ce_kernel<<<1, 1024>>>(out);
}

// round 12
// speedup vs baseline: 1.3242x; 1.1052x over previous
#include <cuda_runtime.h>
#include <cuda_bf16.h>
#include <cstdint>

// ---------------------------------------------------------------------------
// Problem constants (fixed shapes)
// ---------------------------------------------------------------------------
#define B_    96
#define N1    196      // image tokens (valid rows)
#define N2    77       // text tokens (valid cols)
#define DIM   512
#define MPAD  224      // image rows padded to 7 x 32 (zeros beyond 196)
#define NPAD  80       // text rows padded to 10 x 8 (zeros beyond 77)
#define Gg    2        // text blocks per CTA (one per n-half)
#define KC    64       // K elements per pipeline stage
#define KSTEPS 8       // 512 / 64
#define NSTAGES 3
#define NWARP 14
#define NTHREADS 448

// smem stage layout: rows of 128B data padded to 144B stride.
// 144B stride = word-stride 36 == 4 (mod 32) -> 8-row ldmatrix groups hit all
// 32 banks exactly once: conflict-free LDSM and conflict-free cp.async stores.
#define ROWB      144
#define A_ROWS    224
#define B_ROWS    160                      // Gg * 80
#define A_BYTES   (A_ROWS * ROWB)          // 32256
#define B_REGION  A_BYTES
#define STAGE_BYTES (A_BYTES + B_ROWS * ROWB)   // 55296
#define CHUNKS    ((A_ROWS + B_ROWS) * 8)  // 3072 x 16B per stage

#define SMEM_COL  (NSTAGES * STAGE_BYTES)        // float[14][80]
#define SMEM_RS   (SMEM_COL + NWARP * NPAD * 4)  // float[14]
#define SMEM_TOTAL (SMEM_RS + NWARP * 4)

// Preconverted bf16 inputs (padded) + logit matrices as device globals
__device__ __nv_bfloat16 g_img[(size_t)B_ * MPAD * DIM];   // 22 MB
__device__ __nv_bfloat16 g_txt[(size_t)B_ * NPAD * DIM];   // 7.9 MB
__device__ float g_i2t[B_ * B_];
__device__ float g_t2i[B_ * B_];

// ---------------------------------------------------------------------------
// PTX helpers (plain sm_103 feature set only: cp.async, ldmatrix, mma.sync)
// ---------------------------------------------------------------------------
__device__ __forceinline__ void cp16(uint32_t dst_smem, const void* src) {
    asm volatile("cp.async.cg.shared.global [%0], [%1], 16;\n" :: "r"(dst_smem), "l"(src));
}
__device__ __forceinline__ void cp_commit() {
    asm volatile("cp.async.commit_group;\n");
}
template <int N>
__device__ __forceinline__ void cp_wait() {
    asm volatile("cp.async.wait_group %0;\n" :: "n"(N));
}

__device__ __forceinline__ void ldsm4(uint32_t& r0, uint32_t& r1, uint32_t& r2, uint32_t& r3,
                                      uint32_t addr) {
    asm volatile("ldmatrix.sync.aligned.m8n8.x4.shared.b16 {%0,%1,%2,%3}, [%4];\n"
                 : "=r"(r0), "=r"(r1), "=r"(r2), "=r"(r3) : "r"(addr));
}

__device__ __forceinline__ void mma16816(float* d,
                                         uint32_t a0, uint32_t a1, uint32_t a2, uint32_t a3,
                                         uint32_t b0, uint32_t b1) {
    asm volatile(
        "mma.sync.aligned.m16n8k16.row.col.f32.bf16.bf16.f32 "
        "{%0,%1,%2,%3}, {%4,%5,%6,%7}, {%8,%9}, {%0,%1,%2,%3};\n"
        : "+f"(d[0]), "+f"(d[1]), "+f"(d[2]), "+f"(d[3])
        : "r"(a0), "r"(a1), "r"(a2), "r"(a3), "r"(b0), "r"(b1));
}

// ---------------------------------------------------------------------------
// Conversion kernels: fp32 -> bf16, zero-pad extra rows
// ---------------------------------------------------------------------------
__global__ void conv_img_kernel(const float* __restrict__ in) {
    int idx = blockIdx.x * blockDim.x + threadIdx.x;    // bf16x2 pair index
    const int TOT = B_ * MPAD * (DIM / 2);
    if (idx >= TOT) return;
    int k2 = idx & (DIM / 2 - 1);
    int rm = idx >> 8;
    int m = rm % MPAD, b = rm / MPAD;
    float2 v = make_float2(0.f, 0.f);
    if (m < N1) v = reinterpret_cast<const float2*>(in)[((size_t)b * N1 + m) * (DIM / 2) + k2];
    reinterpret_cast<__nv_bfloat162*>(g_img)[idx] = __floats2bfloat162_rn(v.x, v.y);
}

__global__ void conv_txt_kernel(const float* __restrict__ in) {
    int idx = blockIdx.x * blockDim.x + threadIdx.x;
    const int TOT = B_ * NPAD * (DIM / 2);
    if (idx >= TOT) return;
    int k2 = idx & (DIM / 2 - 1);
    int rm = idx >> 8;
    int r = rm % NPAD, b = rm / NPAD;
    float2 v = make_float2(0.f, 0.f);
    if (r < N2) v = reinterpret_cast<const float2*>(in)[((size_t)b * N2 + r) * (DIM / 2) + k2];
    reinterpret_cast<__nv_bfloat162*>(g_txt)[idx] = __floats2bfloat162_rn(v.x, v.y);
}

// ---------------------------------------------------------------------------
// Main kernel: one CTA per (bi, 2 bt blocks). 224x(2x80)x512 bf16 mma.sync.
// Warp (mg, h): m-tiles {2mg, 2mg+1} x n-half h (one gb, 10 n-tiles).
// Per k16 per warp: 2 A-LDSM + 5 B-LDSM + 20 HMMA (tensor-bound).
// Grid: (48, 96), 448 threads.
// ---------------------------------------------------------------------------
__global__ void __launch_bounds__(NTHREADS, 1) gemm_pair_kernel() {
    extern __shared__ __align__(128) char smem[];
    const uint32_t sb = (uint32_t)__cvta_generic_to_shared(smem);
    const int tid = threadIdx.x;
    const int w = tid >> 5;
    const int lane = tid & 31;
    const int h = (w >= 7) ? 1 : 0;     // n-half (gb index)
    const int mg = w - 7 * h;           // m-group: rows 32*mg .. 32*mg+31
    const int bt0 = blockIdx.x * Gg;
    const int bi = blockIdx.y;

    const __nv_bfloat16* __restrict__ Ag = g_img + (size_t)bi * MPAD * DIM;
    const __nv_bfloat16* __restrict__ Bg = g_txt + (size_t)bt0 * NPAD * DIM;  // 160 rows

    float acc[2][10][4];                 // [m-tile][n-tile][frag]
#pragma unroll
    for (int mi = 0; mi < 2; mi++)
#pragma unroll
        for (int nt = 0; nt < 10; nt++)
#pragma unroll
            for (int j = 0; j < 4; j++) acc[mi][nt][j] = 0.f;

    // ldmatrix lane-address offsets (within a stage)
    // A m16xk16 tile (mi=0 at rows 32mg, mi=1 at +16)
    const uint32_t a_off0 = (uint32_t)(mg * 32 + (lane & 15)) * ROWB + ((lane >> 4) << 4);
    const uint32_t a_off1 = a_off0 + 16 * ROWB;
    // B x4 covers two n8-tiles (16 rows of this warp's gb)
    const uint32_t b_off = (uint32_t)(((lane >> 4) << 3) + (lane & 7)) * ROWB
                           + (((lane >> 3) & 1) << 4)
                           + B_REGION + (uint32_t)h * (80 * ROWB);

    // stage loader: 3072 16B chunks (A rows 0-223, B rows 0-159)
    auto load_stage = [&](int s) {
        const int k0 = s * KC;
        const uint32_t base = sb + (s % NSTAGES) * STAGE_BYTES;
        for (int i = tid; i < CHUNKS; i += NTHREADS) {
            int row = i >> 3, sub = i & 7;
            uint32_t dst;
            const __nv_bfloat16* src;
            if (row < A_ROWS) {
                dst = base + (uint32_t)row * ROWB + (sub << 4);
                src = Ag + (size_t)row * DIM + k0 + sub * 8;
            } else {
                int r = row - A_ROWS;
                dst = base + B_REGION + (uint32_t)r * ROWB + (sub << 4);
                src = Bg + (size_t)r * DIM + k0 + sub * 8;
            }
            cp16(dst, src);
        }
    };

    // prologue
    load_stage(0); cp_commit();
    load_stage(1); cp_commit();

    // ---- mainloop: single barrier per k64 stage ----
    for (int ks = 0; ks < KSTEPS; ks++) {
        cp_wait<1>();            // stage ks resident (groups retire in order)
        __syncthreads();         // also: everyone finished compute(ks-1)
        if (ks + 2 < KSTEPS) load_stage(ks + 2);   // buffer freed at iter ks-1
        cp_commit();

        const uint32_t stg = sb + (ks % NSTAGES) * STAGE_BYTES;
#pragma unroll
        for (int c = 0; c < 4; c++) {              // k16 sub-chunks
            uint32_t a0, a1, a2, a3, a4, a5, a6, a7;
            ldsm4(a0, a1, a2, a3, stg + a_off0 + c * 32);
            ldsm4(a4, a5, a6, a7, stg + a_off1 + c * 32);
            const uint32_t bbase = stg + b_off + c * 32;
#pragma unroll
            for (int jp = 0; jp < 5; jp++) {       // n-tile pairs
                uint32_t b0, b1, b2, b3;
                ldsm4(b0, b1, b2, b3, bbase + jp * (16 * ROWB));
                mma16816(acc[0][2 * jp],     a0, a1, a2, a3, b0, b1);
                mma16816(acc[0][2 * jp + 1], a0, a1, a2, a3, b2, b3);
                mma16816(acc[1][2 * jp],     a4, a5, a6, a7, b0, b1);
                mma16816(acc[1][2 * jp + 1], a4, a5, a6, a7, b2, b3);
            }
        }
    }

    // ---- epilogue: fused rowmax->mean (i2t) and colmax->mean (t2i) ----
    // Each warp's 32 rows are complete over its gb's 80 cols.
    const float NEG = -3.0e38f;
    float* s_col = (float*)(smem + SMEM_COL);   // [14][80]
    float* s_rs = (float*)(smem + SMEM_RS);     // [14]

    __syncthreads();   // mainloop fully done before reusing smem region

    float rpart = 0.f;
#pragma unroll
    for (int mi = 0; mi < 2; mi++) {
        const int r0 = mg * 32 + mi * 16 + (lane >> 2);
        const int r1 = r0 + 8;
        const bool ok0 = r0 < N1, ok1 = r1 < N1;

        // (1) row maxima over valid cols of this gb
        float rmax0 = NEG, rmax1 = NEG;
#pragma unroll
        for (int nt = 0; nt < 10; nt++) {
#pragma unroll
            for (int j = 0; j < 2; j++) {
                int n = nt * 8 + 2 * (lane & 3) + j;
                if (n < N2) {
                    rmax0 = fmaxf(rmax0, acc[mi][nt][j]);
                    rmax1 = fmaxf(rmax1, acc[mi][nt][2 + j]);
                }
            }
        }
        rmax0 = fmaxf(rmax0, __shfl_xor_sync(0xffffffffu, rmax0, 1));
        rmax0 = fmaxf(rmax0, __shfl_xor_sync(0xffffffffu, rmax0, 2));
        rmax1 = fmaxf(rmax1, __shfl_xor_sync(0xffffffffu, rmax1, 1));
        rmax1 = fmaxf(rmax1, __shfl_xor_sync(0xffffffffu, rmax1, 2));
        if ((lane & 3) == 0) {
            if (ok0) rpart += rmax0;
            if (ok1) rpart += rmax1;
        }
    }
    rpart += __shfl_xor_sync(0xffffffffu, rpart, 16);
    rpart += __shfl_xor_sync(0xffffffffu, rpart, 8);
    rpart += __shfl_xor_sync(0xffffffffu, rpart, 4);
    rpart += __shfl_xor_sync(0xffffffffu, rpart, 2);
    rpart += __shfl_xor_sync(0xffffffffu, rpart, 1);
    if (lane == 0) s_rs[w] = rpart;

    // (2) column maxima over this warp's 32 rows (validity-masked)
    {
        const int r0 = mg * 32 + (lane >> 2);
#pragma unroll
        for (int nt = 0; nt < 10; nt++) {
#pragma unroll
            for (int j = 0; j < 2; j++) {
                float cm = NEG;
#pragma unroll
                for (int mi = 0; mi < 2; mi++) {
                    const int rr0 = r0 + mi * 16, rr1 = rr0 + 8;
                    if (rr0 < N1) cm = fmaxf(cm, acc[mi][nt][j]);
                    if (rr1 < N1) cm = fmaxf(cm, acc[mi][nt][2 + j]);
                }
                cm = fmaxf(cm, __shfl_xor_sync(0xffffffffu, cm, 4));
                cm = fmaxf(cm, __shfl_xor_sync(0xffffffffu, cm, 8));
                cm = fmaxf(cm, __shfl_xor_sync(0xffffffffu, cm, 16));
                if (lane < 4) s_col[w * NPAD + nt * 8 + 2 * lane + j] = cm;
            }
        }
    }
    __syncthreads();

    // final reductions: warp 0 handles h=0, warp 7 handles h=1 (in parallel)
    if (w == 0 || w == 7) {
        const int hh = (w == 7);
        const int base = hh * 7;
        float csum = 0.f;
        for (int n = lane; n < N2; n += 32) {
            float m = s_col[base * NPAD + n];
#pragma unroll
            for (int w2 = 1; w2 < 7; w2++) m = fmaxf(m, s_col[(base + w2) * NPAD + n]);
            csum += m;
        }
        csum += __shfl_xor_sync(0xffffffffu, csum, 16);
        csum += __shfl_xor_sync(0xffffffffu, csum, 8);
        csum += __shfl_xor_sync(0xffffffffu, csum, 4);
        csum += __shfl_xor_sync(0xffffffffu, csum, 2);
        csum += __shfl_xor_sync(0xffffffffu, csum, 1);
        if (lane == 0) {
            float rs = 0.f;
#pragma unroll
            for (int w2 = 0; w2 < 7; w2++) rs += s_rs[base + w2];
            g_i2t[bi * B_ + bt0 + hh] = rs * (1.0f / N1);
            g_t2i[(bt0 + hh) * B_ + bi] = csum * (1.0f / N2);
        }
    }
}

// ---------------------------------------------------------------------------
// Final cross-entropy: 32 warps, one row-task per warp (192 tasks total)
// ---------------------------------------------------------------------------
__global__ void ce_kernel(float* __restrict__ out) {
    __shared__ float spart[32];
    int w = threadIdx.x >> 5, lane = threadIdx.x & 31;
    float acc = 0.f;
    for (int task = w; task < 2 * B_; task += 32) {
        const float* rowp = (task < B_) ? (g_i2t + task * B_) : (g_t2i + (task - B_) * B_);
        int b = (task < B_) ? task : task - B_;
        float v0 = rowp[lane], v1 = rowp[lane + 32], v2 = rowp[lane + 64];
        float mx = fmaxf(v0, fmaxf(v1, v2));
        mx = fmaxf(mx, __shfl_xor_sync(0xffffffffu, mx, 16));
        mx = fmaxf(mx, __shfl_xor_sync(0xffffffffu, mx, 8));
        mx = fmaxf(mx, __shfl_xor_sync(0xffffffffu, mx, 4));
        mx = fmaxf(mx, __shfl_xor_sync(0xffffffffu, mx, 2));
        mx = fmaxf(mx, __shfl_xor_sync(0xffffffffu, mx, 1));
        float s = expf(v0 - mx) + expf(v1 - mx) + expf(v2 - mx);
        s += __shfl_xor_sync(0xffffffffu, s, 16);
        s += __shfl_xor_sync(0xffffffffu, s, 8);
        s += __shfl_xor_sync(0xffffffffu, s, 4);
        s += __shfl_xor_sync(0xffffffffu, s, 2);
        s += __shfl_xor_sync(0xffffffffu, s, 1);
        if (lane == 0) acc += mx + logf(s) - rowp[b];
    }
    if (lane == 0) spart[w] = acc;
    __syncthreads();
    if (w == 0) {
        float v = spart[lane];
        v += __shfl_xor_sync(0xffffffffu, v, 16);
        v += __shfl_xor_sync(0xffffffffu, v, 8);
        v += __shfl_xor_sync(0xffffffffu, v, 4);
        v += __shfl_xor_sync(0xffffffffu, v, 2);
        v += __shfl_xor_sync(0xffffffffu, v, 1);
        if (lane == 0) out[0] = 0.5f * v * (1.0f / B_);
    }
}

// ---------------------------------------------------------------------------
extern "C" void kernel_launch(void* const* d_in, const int* in_sizes, int n_in,
                              void* d_out, int out_size) {
    const float* img = (const float*)d_in[0];   // [96, 196, 512] fp32
    const float* txt = (const float*)d_in[1];   // [96, 77, 512] fp32
    float* out = (float*)d_out;

    cudaFuncSetAttribute(gemm_pair_kernel,
                         cudaFuncAttributeMaxDynamicSharedMemorySize, SMEM_TOTAL);

    {
        int tot = B_ * MPAD * (DIM / 2);
        conv_img_kernel<<<(tot + 255) / 256, 256>>>(img);
    }
    {
        int tot = B_ * NPAD * (DIM / 2);
        conv_txt_kernel<<<(tot + 255) / 256, 256>>>(txt);
    }
    gemm_pair_kernel<<<dim3(B_ / Gg, B_), NTHREADS, SMEM_TOTAL>>>();
    ce_kernel<<<1, 1024>>>(out);
}

// round 16
// speedup vs baseline: 1.4562x; 1.0997x over previous
#include <cuda_runtime.h>
#include <cuda_bf16.h>
#include <cstdint>

// ---------------------------------------------------------------------------
// Problem constants (fixed shapes)
// ---------------------------------------------------------------------------
#define B_    96
#define N1    196      // image tokens (valid rows)
#define N2    77       // text tokens (valid cols)
#define DIM   512
#define MPAD  208      // image rows padded to 13 x 16 (zeros beyond 196)
#define NPAD  80       // text rows padded to 10 x 8 (zeros beyond 77)
#define Gg    2        // text blocks per CTA (one per n-half)
#define KC    64       // K elements per pipeline stage
#define KSTEPS 8       // 512 / 64
#define NSTAGES 3
#define NWARP 14
#define NTHREADS 448

// smem stage layout: rows of 128B data padded to 144B stride.
// 144B stride = word-stride 36 == 4 (mod 32) -> 8-row ldmatrix groups hit all
// 32 banks exactly once: conflict-free LDSM and conflict-free cp.async stores.
#define ROWB      144
#define A_ROWS    208
#define B_ROWS    160                      // Gg * 80
#define A_BYTES   (A_ROWS * ROWB)          // 29952
#define B_REGION  A_BYTES
#define STAGE_BYTES (A_BYTES + B_ROWS * ROWB)   // 52992
#define CHUNKS    ((A_ROWS + B_ROWS) * 8)  // 2944 x 16B per stage

#define SMEM_COL  (NSTAGES * STAGE_BYTES)        // float[14][80]
#define SMEM_RS   (SMEM_COL + NWARP * NPAD * 4)  // float[14]
#define SMEM_TOTAL (SMEM_RS + NWARP * 4)

// Preconverted bf16 inputs (padded) + logit matrices as device globals
__device__ __nv_bfloat16 g_img[(size_t)B_ * MPAD * DIM];   // 20.4 MB
__device__ __nv_bfloat16 g_txt[(size_t)B_ * NPAD * DIM];   // 7.9 MB
__device__ float g_i2t[B_ * B_];
__device__ float g_t2i[B_ * B_];

// ---------------------------------------------------------------------------
// PTX helpers (plain sm_103 feature set only: cp.async, ldmatrix, mma.sync)
// ---------------------------------------------------------------------------
__device__ __forceinline__ void cp16(uint32_t dst_smem, const void* src) {
    asm volatile("cp.async.cg.shared.global [%0], [%1], 16;\n" :: "r"(dst_smem), "l"(src));
}
__device__ __forceinline__ void cp_commit() {
    asm volatile("cp.async.commit_group;\n");
}
template <int N>
__device__ __forceinline__ void cp_wait() {
    asm volatile("cp.async.wait_group %0;\n" :: "n"(N));
}

__device__ __forceinline__ void ldsm4(uint32_t& r0, uint32_t& r1, uint32_t& r2, uint32_t& r3,
                                      uint32_t addr) {
    asm volatile("ldmatrix.sync.aligned.m8n8.x4.shared.b16 {%0,%1,%2,%3}, [%4];\n"
                 : "=r"(r0), "=r"(r1), "=r"(r2), "=r"(r3) : "r"(addr));
}

__device__ __forceinline__ void mma16816(float* d,
                                         uint32_t a0, uint32_t a1, uint32_t a2, uint32_t a3,
                                         uint32_t b0, uint32_t b1) {
    asm volatile(
        "mma.sync.aligned.m16n8k16.row.col.f32.bf16.bf16.f32 "
        "{%0,%1,%2,%3}, {%4,%5,%6,%7}, {%8,%9}, {%0,%1,%2,%3};\n"
        : "+f"(d[0]), "+f"(d[1]), "+f"(d[2]), "+f"(d[3])
        : "r"(a0), "r"(a1), "r"(a2), "r"(a3), "r"(b0), "r"(b1));
}

// ---------------------------------------------------------------------------
// Conversion kernels: fp32 -> bf16, zero-pad extra rows
// ---------------------------------------------------------------------------
__global__ void conv_img_kernel(const float* __restrict__ in) {
    int idx = blockIdx.x * blockDim.x + threadIdx.x;    // bf16x2 pair index
    const int TOT = B_ * MPAD * (DIM / 2);
    if (idx >= TOT) return;
    int k2 = idx & (DIM / 2 - 1);
    int rm = idx >> 8;
    int m = rm % MPAD, b = rm / MPAD;
    float2 v = make_float2(0.f, 0.f);
    if (m < N1) v = reinterpret_cast<const float2*>(in)[((size_t)b * N1 + m) * (DIM / 2) + k2];
    reinterpret_cast<__nv_bfloat162*>(g_img)[idx] = __floats2bfloat162_rn(v.x, v.y);
}

__global__ void conv_txt_kernel(const float* __restrict__ in) {
    int idx = blockIdx.x * blockDim.x + threadIdx.x;
    const int TOT = B_ * NPAD * (DIM / 2);
    if (idx >= TOT) return;
    int k2 = idx & (DIM / 2 - 1);
    int rm = idx >> 8;
    int r = rm % NPAD, b = rm / NPAD;
    float2 v = make_float2(0.f, 0.f);
    if (r < N2) v = reinterpret_cast<const float2*>(in)[((size_t)b * N2 + r) * (DIM / 2) + k2];
    reinterpret_cast<__nv_bfloat162*>(g_txt)[idx] = __floats2bfloat162_rn(v.x, v.y);
}

// ---------------------------------------------------------------------------
// Main kernel: one CTA per (bi, 2 bt blocks). 208x(2x80)x512 bf16 mma.sync.
// Warp tasks (13 m-tiles x 2 n-halves = 26 tile-tasks):
//   w0-5:  h=0, m-tiles {2w, 2w+1}        (pair task, 80 HMMA/stage)
//   w6-11: h=1, m-tiles {2(w-6), 2(w-6)+1}
//   w12:   h=0, m-tile 12 (single task, 40 HMMA/stage)  -> SMSP0
//   w13:   h=1, m-tile 12                               -> SMSP1
// SMSP HMMA loads: 280/280/240/240 (was 320/320/240/240 at MPAD=224).
// k16-chunk order rotated by (w & 3) to de-phase LDSM bursts across warps.
// Grid: (48, 96), 448 threads.
// ---------------------------------------------------------------------------
__global__ void __launch_bounds__(NTHREADS, 1) gemm_pair_kernel() {
    extern __shared__ __align__(128) char smem[];
    const uint32_t sb = (uint32_t)__cvta_generic_to_shared(smem);
    const int tid = threadIdx.x;
    const int w = tid >> 5;
    const int lane = tid & 31;
    const int bt0 = blockIdx.x * Gg;
    const int bi = blockIdx.y;

    int h, m_base, nmt;
    if (w < 6)       { h = 0; m_base = w * 32;        nmt = 2; }
    else if (w < 12) { h = 1; m_base = (w - 6) * 32;  nmt = 2; }
    else             { h = w - 12; m_base = 192;      nmt = 1; }

    const __nv_bfloat16* __restrict__ Ag = g_img + (size_t)bi * MPAD * DIM;
    const __nv_bfloat16* __restrict__ Bg = g_txt + (size_t)bt0 * NPAD * DIM;  // 160 rows

    float acc[2][10][4];                 // [m-tile][n-tile][frag]
#pragma unroll
    for (int mi = 0; mi < 2; mi++)
#pragma unroll
        for (int nt = 0; nt < 10; nt++)
#pragma unroll
            for (int j = 0; j < 4; j++) acc[mi][nt][j] = 0.f;

    // ldmatrix lane-address offsets (within a stage)
    const uint32_t a_off0 = (uint32_t)(m_base + (lane & 15)) * ROWB + ((lane >> 4) << 4);
    const uint32_t a_off1 = a_off0 + 16 * ROWB;
    const uint32_t b_off = (uint32_t)(((lane >> 4) << 3) + (lane & 7)) * ROWB
                           + (((lane >> 3) & 1) << 4)
                           + B_REGION + (uint32_t)h * (80 * ROWB);

    // stage loader: 2944 16B chunks (A rows 0-207, B rows 0-159)
    auto load_stage = [&](int s) {
        const int k0 = s * KC;
        const uint32_t base = sb + (s % NSTAGES) * STAGE_BYTES;
        for (int i = tid; i < CHUNKS; i += NTHREADS) {
            int row = i >> 3, sub = i & 7;
            uint32_t dst;
            const __nv_bfloat16* src;
            if (row < A_ROWS) {
                dst = base + (uint32_t)row * ROWB + (sub << 4);
                src = Ag + (size_t)row * DIM + k0 + sub * 8;
            } else {
                int r = row - A_ROWS;
                dst = base + B_REGION + (uint32_t)r * ROWB + (sub << 4);
                src = Bg + (size_t)r * DIM + k0 + sub * 8;
            }
            cp16(dst, src);
        }
    };

    // prologue
    load_stage(0); cp_commit();
    load_stage(1); cp_commit();

    // ---- mainloop: single barrier per k64 stage ----
#pragma unroll 1
    for (int ks = 0; ks < KSTEPS; ks++) {
        cp_wait<1>();            // stage ks resident (groups retire in order)
        __syncthreads();         // also: everyone finished compute(ks-1)
        if (ks + 2 < KSTEPS) load_stage(ks + 2);   // buffer freed at iter ks-1
        cp_commit();

        const uint32_t stg = sb + (ks % NSTAGES) * STAGE_BYTES;
        if (nmt == 2) {
#pragma unroll
            for (int ci = 0; ci < 4; ci++) {       // k16 sub-chunks, de-phased
                const int c = (ci + (w & 3)) & 3;
                uint32_t a0, a1, a2, a3, a4, a5, a6, a7;
                ldsm4(a0, a1, a2, a3, stg + a_off0 + c * 32);
                ldsm4(a4, a5, a6, a7, stg + a_off1 + c * 32);
                const uint32_t bbase = stg + b_off + c * 32;
#pragma unroll
                for (int jp = 0; jp < 5; jp++) {   // n-tile pairs
                    uint32_t b0, b1, b2, b3;
                    ldsm4(b0, b1, b2, b3, bbase + jp * (16 * ROWB));
                    mma16816(acc[0][2 * jp],     a0, a1, a2, a3, b0, b1);
                    mma16816(acc[0][2 * jp + 1], a0, a1, a2, a3, b2, b3);
                    mma16816(acc[1][2 * jp],     a4, a5, a6, a7, b0, b1);
                    mma16816(acc[1][2 * jp + 1], a4, a5, a6, a7, b2, b3);
                }
            }
        } else {
#pragma unroll
            for (int ci = 0; ci < 4; ci++) {
                const int c = (ci + (w & 3)) & 3;
                uint32_t a0, a1, a2, a3;
                ldsm4(a0, a1, a2, a3, stg + a_off0 + c * 32);
                const uint32_t bbase = stg + b_off + c * 32;
#pragma unroll
                for (int jp = 0; jp < 5; jp++) {
                    uint32_t b0, b1, b2, b3;
                    ldsm4(b0, b1, b2, b3, bbase + jp * (16 * ROWB));
                    mma16816(acc[0][2 * jp],     a0, a1, a2, a3, b0, b1);
                    mma16816(acc[0][2 * jp + 1], a0, a1, a2, a3, b2, b3);
                }
            }
        }
    }

    // ---- epilogue: fused rowmax->mean (i2t) and colmax->mean (t2i) ----
    const float NEG = -3.0e38f;
    float* s_col = (float*)(smem + SMEM_COL);   // [14][80]
    float* s_rs = (float*)(smem + SMEM_RS);     // [14]

    // (1) row maxima over valid cols of this warp's gb -> per-warp partial sum
    float rpart = 0.f;
    for (int mi = 0; mi < nmt; mi++) {
        const int r0 = m_base + mi * 16 + (lane >> 2);
        const int r1 = r0 + 8;
        const bool ok0 = r0 < N1, ok1 = r1 < N1;

        float rmax0 = NEG, rmax1 = NEG;
#pragma unroll
        for (int nt = 0; nt < 10; nt++) {
#pragma unroll
            for (int j = 0; j < 2; j++) {
                int n = nt * 8 + 2 * (lane & 3) + j;
                if (n < N2) {
                    rmax0 = fmaxf(rmax0, acc[mi][nt][j]);
                    rmax1 = fmaxf(rmax1, acc[mi][nt][2 + j]);
                }
            }
        }
        rmax0 = fmaxf(rmax0, __shfl_xor_sync(0xffffffffu, rmax0, 1));
        rmax0 = fmaxf(rmax0, __shfl_xor_sync(0xffffffffu, rmax0, 2));
        rmax1 = fmaxf(rmax1, __shfl_xor_sync(0xffffffffu, rmax1, 1));
        rmax1 = fmaxf(rmax1, __shfl_xor_sync(0xffffffffu, rmax1, 2));
        if ((lane & 3) == 0) {
            if (ok0) rpart += rmax0;
            if (ok1) rpart += rmax1;
        }
    }
    rpart += __shfl_xor_sync(0xffffffffu, rpart, 16);
    rpart += __shfl_xor_sync(0xffffffffu, rpart, 8);
    rpart += __shfl_xor_sync(0xffffffffu, rpart, 4);
    rpart += __shfl_xor_sync(0xffffffffu, rpart, 2);
    rpart += __shfl_xor_sync(0xffffffffu, rpart, 1);
    if (lane == 0) s_rs[w] = rpart;

    // (2) column maxima over this warp's rows (validity-masked)
    {
        const int r0 = m_base + (lane >> 2);
#pragma unroll
        for (int nt = 0; nt < 10; nt++) {
#pragma unroll
            for (int j = 0; j < 2; j++) {
                float cm = NEG;
                for (int mi = 0; mi < nmt; mi++) {
                    const int rr0 = r0 + mi * 16, rr1 = rr0 + 8;
                    if (rr0 < N1) cm = fmaxf(cm, acc[mi][nt][j]);
                    if (rr1 < N1) cm = fmaxf(cm, acc[mi][nt][2 + j]);
                }
                cm = fmaxf(cm, __shfl_xor_sync(0xffffffffu, cm, 4));
                cm = fmaxf(cm, __shfl_xor_sync(0xffffffffu, cm, 8));
                cm = fmaxf(cm, __shfl_xor_sync(0xffffffffu, cm, 16));
                if (lane < 4) s_col[w * NPAD + nt * 8 + 2 * lane + j] = cm;
            }
        }
    }
    __syncthreads();

    // final reductions: warp 0 handles h=0 (warps 0-5,12), warp 6 handles h=1 (6-11,13)
    if (w == 0 || w == 6) {
        const int hh = (w == 6);
        const int wbase = hh * 6;
        const int wext = 12 + hh;
        float csum = 0.f;
        for (int n = lane; n < N2; n += 32) {
            float m = s_col[wext * NPAD + n];
#pragma unroll
            for (int w2 = 0; w2 < 6; w2++) m = fmaxf(m, s_col[(wbase + w2) * NPAD + n]);
            csum += m;
        }
        csum += __shfl_xor_sync(0xffffffffu, csum, 16);
        csum += __shfl_xor_sync(0xffffffffu, csum, 8);
        csum += __shfl_xor_sync(0xffffffffu, csum, 4);
        csum += __shfl_xor_sync(0xffffffffu, csum, 2);
        csum += __shfl_xor_sync(0xffffffffu, csum, 1);
        if (lane == 0) {
            float rs = s_rs[wext];
#pragma unroll
            for (int w2 = 0; w2 < 6; w2++) rs += s_rs[wbase + w2];
            g_i2t[bi * B_ + bt0 + hh] = rs * (1.0f / N1);
            g_t2i[(bt0 + hh) * B_ + bi] = csum * (1.0f / N2);
        }
    }
}

// ---------------------------------------------------------------------------
// Final cross-entropy: 32 warps, one row-task per warp (192 tasks total)
// ---------------------------------------------------------------------------
__global__ void ce_kernel(float* __restrict__ out) {
    __shared__ float spart[32];
    int w = threadIdx.x >> 5, lane = threadIdx.x & 31;
    float acc = 0.f;
    for (int task = w; task < 2 * B_; task += 32) {
        const float* rowp = (task < B_) ? (g_i2t + task * B_) : (g_t2i + (task - B_) * B_);
        int b = (task < B_) ? task : task - B_;
        float v0 = rowp[lane], v1 = rowp[lane + 32], v2 = rowp[lane + 64];
        float mx = fmaxf(v0, fmaxf(v1, v2));
        mx = fmaxf(mx, __shfl_xor_sync(0xffffffffu, mx, 16));
        mx = fmaxf(mx, __shfl_xor_sync(0xffffffffu, mx, 8));
        mx = fmaxf(mx, __shfl_xor_sync(0xffffffffu, mx, 4));
        mx = fmaxf(mx, __shfl_xor_sync(0xffffffffu, mx, 2));
        mx = fmaxf(mx, __shfl_xor_sync(0xffffffffu, mx, 1));
        float s = expf(v0 - mx) + expf(v1 - mx) + expf(v2 - mx);
        s += __shfl_xor_sync(0xffffffffu, s, 16);
        s += __shfl_xor_sync(0xffffffffu, s, 8);
        s += __shfl_xor_sync(0xffffffffu, s, 4);
        s += __shfl_xor_sync(0xffffffffu, s, 2);
        s += __shfl_xor_sync(0xffffffffu, s, 1);
        if (lane == 0) acc += mx + logf(s) - rowp[b];
    }
    if (lane == 0) spart[w] = acc;
    __syncthreads();
    if (w == 0) {
        float v = spart[lane];
        v += __shfl_xor_sync(0xffffffffu, v, 16);
        v += __shfl_xor_sync(0xffffffffu, v, 8);
        v += __shfl_xor_sync(0xffffffffu, v, 4);
        v += __shfl_xor_sync(0xffffffffu, v, 2);
        v += __shfl_xor_sync(0xffffffffu, v, 1);
        if (lane == 0) out[0] = 0.5f * v * (1.0f / B_);
    }
}

// ---------------------------------------------------------------------------
extern "C" void kernel_launch(void* const* d_in, const int* in_sizes, int n_in,
                              void* d_out, int out_size) {
    const float* img = (const float*)d_in[0];   // [96, 196, 512] fp32
    const float* txt = (const float*)d_in[1];   // [96, 77, 512] fp32
    float* out = (float*)d_out;

    cudaFuncSetAttribute(gemm_pair_kernel,
                         cudaFuncAttributeMaxDynamicSharedMemorySize, SMEM_TOTAL);

    {
        int tot = B_ * MPAD * (DIM / 2);
        conv_img_kernel<<<(tot + 255) / 256, 256>>>(img);
    }
    {
        int tot = B_ * NPAD * (DIM / 2);
        conv_txt_kernel<<<(tot + 255) / 256, 256>>>(txt);
    }
    gemm_pair_kernel<<<dim3(B_ / Gg, B_), NTHREADS, SMEM_TOTAL>>>();
    ce_kernel<<<1, 1024>>>(out);
}

// round 17
// speedup vs baseline: 1.6401x; 1.1263x over previous
#include <cuda_runtime.h>
#include <cuda_bf16.h>
#include <cstdint>

// ---------------------------------------------------------------------------
// Problem constants (fixed shapes)
// ---------------------------------------------------------------------------
#define B_    96
#define N1    196      // image tokens (valid rows)
#define N2    77       // text tokens (valid cols)
#define DIM   512
#define MPAD  208      // image rows padded to 13 x 16 (zeros beyond 196)
#define NPAD  80       // text rows padded to 10 x 8 (zeros beyond 77)
#define Gg    2        // text blocks per CTA (one per n-half)
#define KC    64       // K elements per pipeline stage
#define KSTEPS 8       // 512 / 64
#define NSTAGES 3
#define NCWARP 14      // consumer warps
#define NTHREADS 512   // 14 consumer + 2 producer warps
#define NPROD  64      // producer threads

// smem stage layout: rows of 128B data padded to 144B stride.
// 144B stride = word-stride 36 == 4 (mod 32) -> 8-row ldmatrix groups hit all
// 32 banks exactly once: conflict-free LDSM and conflict-free cp.async stores.
#define ROWB      144
#define A_ROWS    208
#define B_ROWS    160                      // Gg * 80
#define A_BYTES   (A_ROWS * ROWB)          // 29952
#define B_REGION  A_BYTES
#define STAGE_BYTES (A_BYTES + B_ROWS * ROWB)   // 52992
#define CHUNKS    ((A_ROWS + B_ROWS) * 8)  // 2944 x 16B per stage

#define SMEM_COL  (NSTAGES * STAGE_BYTES)          // float[14][80] @ 158976
#define SMEM_RS   (SMEM_COL + NCWARP * NPAD * 4)   // float[14]
#define SMEM_MBAR ((SMEM_RS + NCWARP * 4 + 15) & ~15)  // full[3], empty[3] x 8B
#define SMEM_TOTAL (SMEM_MBAR + 48)

// Preconverted bf16 inputs (padded) + logit matrices as device globals
__device__ __nv_bfloat16 g_img[(size_t)B_ * MPAD * DIM];   // 20.4 MB
__device__ __nv_bfloat16 g_txt[(size_t)B_ * NPAD * DIM];   // 7.9 MB
__device__ float g_i2t[B_ * B_];
__device__ float g_t2i[B_ * B_];

// ---------------------------------------------------------------------------
// PTX helpers (plain sm_103 feature set: cp.async, ldmatrix, mma.sync, mbarrier)
// ---------------------------------------------------------------------------
__device__ __forceinline__ void cp16(uint32_t dst_smem, const void* src) {
    asm volatile("cp.async.cg.shared.global [%0], [%1], 16;\n" :: "r"(dst_smem), "l"(src));
}

__device__ __forceinline__ void ldsm4(uint32_t& r0, uint32_t& r1, uint32_t& r2, uint32_t& r3,
                                      uint32_t addr) {
    asm volatile("ldmatrix.sync.aligned.m8n8.x4.shared.b16 {%0,%1,%2,%3}, [%4];\n"
                 : "=r"(r0), "=r"(r1), "=r"(r2), "=r"(r3) : "r"(addr));
}

__device__ __forceinline__ void mma16816(float* d,
                                         uint32_t a0, uint32_t a1, uint32_t a2, uint32_t a3,
                                         uint32_t b0, uint32_t b1) {
    asm volatile(
        "mma.sync.aligned.m16n8k16.row.col.f32.bf16.bf16.f32 "
        "{%0,%1,%2,%3}, {%4,%5,%6,%7}, {%8,%9}, {%0,%1,%2,%3};\n"
        : "+f"(d[0]), "+f"(d[1]), "+f"(d[2]), "+f"(d[3])
        : "r"(a0), "r"(a1), "r"(a2), "r"(a3), "r"(b0), "r"(b1));
}

#define MBARRIER_INIT(mbar_smem_addr, count) \
    asm volatile("mbarrier.init.shared.b64 [%0], %1;" \
        :: "r"((uint32_t)(mbar_smem_addr)), "r"((uint32_t)(count)) : "memory")

#define MBARRIER_ARRIVE(mbar_smem_addr) \
    asm volatile("mbarrier.arrive.shared.b64 _, [%0];" \
        :: "r"((uint32_t)(mbar_smem_addr)) : "memory")

#define CPASYNC_MBAR_ARRIVE(mbar_smem_addr) \
    asm volatile("cp.async.mbarrier.arrive.noinc.shared.b64 [%0];" \
        :: "r"((uint32_t)(mbar_smem_addr)) : "memory")

#define MBARRIER_WAIT_PARITY(mbar_smem_addr, phase_parity) do { \
    uint32_t _mbar = (uint32_t)(mbar_smem_addr); \
    uint32_t _parity = (uint32_t)(phase_parity); \
    uint32_t _done; \
    asm volatile( \
        "{\n\t.reg .pred p;\n\t" \
        "mbarrier.try_wait.parity.acquire.cta.shared::cta.b64 p, [%1], %2;\n\t" \
        "selp.b32 %0, 1, 0, p;\n\t}" \
        : "=r"(_done) : "r"(_mbar), "r"(_parity) : "memory"); \
    if (!_done) { \
        asm volatile( \
            "{\n\t.reg .pred P1;\n\t" \
            "WAIT_LOOP_%=:\n\t" \
            "mbarrier.try_wait.parity.acquire.cta.shared::cta.b64 P1, [%0], %1, 0x989680;\n\t" \
            "@P1 bra.uni WAIT_DONE_%=;\n\t" \
            "bra.uni WAIT_LOOP_%=;\n\t" \
            "WAIT_DONE_%=:\n\t}" \
            :: "r"(_mbar), "r"(_parity) : "memory"); \
    } \
} while (0)

// ---------------------------------------------------------------------------
// Conversion kernels: fp32 -> bf16, zero-pad extra rows
// ---------------------------------------------------------------------------
__global__ void conv_img_kernel(const float* __restrict__ in) {
    int idx = blockIdx.x * blockDim.x + threadIdx.x;    // bf16x2 pair index
    const int TOT = B_ * MPAD * (DIM / 2);
    if (idx >= TOT) return;
    int k2 = idx & (DIM / 2 - 1);
    int rm = idx >> 8;
    int m = rm % MPAD, b = rm / MPAD;
    float2 v = make_float2(0.f, 0.f);
    if (m < N1) v = reinterpret_cast<const float2*>(in)[((size_t)b * N1 + m) * (DIM / 2) + k2];
    reinterpret_cast<__nv_bfloat162*>(g_img)[idx] = __floats2bfloat162_rn(v.x, v.y);
}

__global__ void conv_txt_kernel(const float* __restrict__ in) {
    int idx = blockIdx.x * blockDim.x + threadIdx.x;
    const int TOT = B_ * NPAD * (DIM / 2);
    if (idx >= TOT) return;
    int k2 = idx & (DIM / 2 - 1);
    int rm = idx >> 8;
    int r = rm % NPAD, b = rm / NPAD;
    float2 v = make_float2(0.f, 0.f);
    if (r < N2) v = reinterpret_cast<const float2*>(in)[((size_t)b * N2 + r) * (DIM / 2) + k2];
    reinterpret_cast<__nv_bfloat162*>(g_txt)[idx] = __floats2bfloat162_rn(v.x, v.y);
}

// ---------------------------------------------------------------------------
// Main kernel: one CTA per (bi, 2 bt blocks). 208x(2x80)x512 bf16 mma.sync.
// Warp-specialized: w14-15 produce (cp.async), w0-13 consume (LDSM+HMMA).
// No block barrier in the mainloop: consumers gate on per-buffer mbarriers
// and skew freely (bounded by the 3-buffer ring), overlapping crossbar
// traffic with tensor work.
// Consumer tasks: w0-5 h=0 m-tiles{2w,2w+1}; w6-11 h=1; w12/w13 m-tile 12.
// Grid: (48, 96), 512 threads.
// ---------------------------------------------------------------------------
__global__ void __launch_bounds__(NTHREADS, 1) gemm_pair_kernel() {
    extern __shared__ __align__(128) char smem[];
    const uint32_t sb = (uint32_t)__cvta_generic_to_shared(smem);
    const int tid = threadIdx.x;
    const int w = tid >> 5;
    const int lane = tid & 31;
    const int bt0 = blockIdx.x * Gg;
    const int bi = blockIdx.y;

    const __nv_bfloat16* __restrict__ Ag = g_img + (size_t)bi * MPAD * DIM;
    const __nv_bfloat16* __restrict__ Bg = g_txt + (size_t)bt0 * NPAD * DIM;  // 160 rows

    const uint32_t mb_full = sb + SMEM_MBAR;        // full[b] at +8b
    const uint32_t mb_empty = sb + SMEM_MBAR + 24;  // empty[b] at +8b

    if (tid == 0) {
#pragma unroll
        for (int b = 0; b < NSTAGES; b++) {
            MBARRIER_INIT(mb_full + b * 8, NPROD);    // one arrive per producer thread
            MBARRIER_INIT(mb_empty + b * 8, NCWARP);  // one arrive per consumer warp
        }
    }
    __syncthreads();

    if (w >= NCWARP) {
        // ---------------- producer warps ----------------
        const int ptid = tid - NCWARP * 32;   // 0..63
#pragma unroll 1
        for (int s = 0; s < KSTEPS; s++) {
            const int b = s % NSTAGES;
            if (s >= NSTAGES)
                MBARRIER_WAIT_PARITY(mb_empty + b * 8, ((s - NSTAGES) / NSTAGES) & 1);
            const int k0 = s * KC;
            const uint32_t base = sb + b * STAGE_BYTES;
            for (int i = ptid; i < CHUNKS; i += NPROD) {
                int row = i >> 3, sub = i & 7;
                uint32_t dst;
                const __nv_bfloat16* src;
                if (row < A_ROWS) {
                    dst = base + (uint32_t)row * ROWB + (sub << 4);
                    src = Ag + (size_t)row * DIM + k0 + sub * 8;
                } else {
                    int r = row - A_ROWS;
                    dst = base + B_REGION + (uint32_t)r * ROWB + (sub << 4);
                    src = Bg + (size_t)r * DIM + k0 + sub * 8;
                }
                cp16(dst, src);
            }
            CPASYNC_MBAR_ARRIVE(mb_full + b * 8);   // async arrive when this thread's cps land
        }
    } else {
        // ---------------- consumer warps ----------------
        int h, m_base, nmt;
        if (w < 6)       { h = 0; m_base = w * 32;        nmt = 2; }
        else if (w < 12) { h = 1; m_base = (w - 6) * 32;  nmt = 2; }
        else             { h = w - 12; m_base = 192;      nmt = 1; }

        float acc[2][10][4];
#pragma unroll
        for (int mi = 0; mi < 2; mi++)
#pragma unroll
            for (int nt = 0; nt < 10; nt++)
#pragma unroll
                for (int j = 0; j < 4; j++) acc[mi][nt][j] = 0.f;

        const uint32_t a_off0 = (uint32_t)(m_base + (lane & 15)) * ROWB + ((lane >> 4) << 4);
        const uint32_t a_off1 = a_off0 + 16 * ROWB;
        const uint32_t b_off = (uint32_t)(((lane >> 4) << 3) + (lane & 7)) * ROWB
                               + (((lane >> 3) & 1) << 4)
                               + B_REGION + (uint32_t)h * (80 * ROWB);

#pragma unroll 1
        for (int s = 0; s < KSTEPS; s++) {
            const int b = s % NSTAGES;
            MBARRIER_WAIT_PARITY(mb_full + b * 8, (s / NSTAGES) & 1);
            const uint32_t stg = sb + b * STAGE_BYTES;
            if (nmt == 2) {
#pragma unroll
                for (int ci = 0; ci < 4; ci++) {       // k16 sub-chunks, de-phased
                    const int c = (ci + (w & 3)) & 3;
                    uint32_t a0, a1, a2, a3, a4, a5, a6, a7;
                    ldsm4(a0, a1, a2, a3, stg + a_off0 + c * 32);
                    ldsm4(a4, a5, a6, a7, stg + a_off1 + c * 32);
                    const uint32_t bbase = stg + b_off + c * 32;
#pragma unroll
                    for (int jp = 0; jp < 5; jp++) {   // n-tile pairs
                        uint32_t b0, b1, b2, b3;
                        ldsm4(b0, b1, b2, b3, bbase + jp * (16 * ROWB));
                        mma16816(acc[0][2 * jp],     a0, a1, a2, a3, b0, b1);
                        mma16816(acc[0][2 * jp + 1], a0, a1, a2, a3, b2, b3);
                        mma16816(acc[1][2 * jp],     a4, a5, a6, a7, b0, b1);
                        mma16816(acc[1][2 * jp + 1], a4, a5, a6, a7, b2, b3);
                    }
                }
            } else {
#pragma unroll
                for (int ci = 0; ci < 4; ci++) {
                    const int c = (ci + (w & 3)) & 3;
                    uint32_t a0, a1, a2, a3;
                    ldsm4(a0, a1, a2, a3, stg + a_off0 + c * 32);
                    const uint32_t bbase = stg + b_off + c * 32;
#pragma unroll
                    for (int jp = 0; jp < 5; jp++) {
                        uint32_t b0, b1, b2, b3;
                        ldsm4(b0, b1, b2, b3, bbase + jp * (16 * ROWB));
                        mma16816(acc[0][2 * jp],     a0, a1, a2, a3, b0, b1);
                        mma16816(acc[0][2 * jp + 1], a0, a1, a2, a3, b2, b3);
                    }
                }
            }
            __syncwarp();
            if (lane == 0) MBARRIER_ARRIVE(mb_empty + b * 8);
        }

        // ---- epilogue: fused rowmax->mean (i2t) and colmax->mean (t2i) ----
        const float NEG = -3.0e38f;
        float* s_col = (float*)(smem + SMEM_COL);   // [14][80]
        float* s_rs = (float*)(smem + SMEM_RS);     // [14]

        float rpart = 0.f;
        for (int mi = 0; mi < nmt; mi++) {
            const int r0 = m_base + mi * 16 + (lane >> 2);
            const int r1 = r0 + 8;
            const bool ok0 = r0 < N1, ok1 = r1 < N1;

            float rmax0 = NEG, rmax1 = NEG;
#pragma unroll
            for (int nt = 0; nt < 10; nt++) {
#pragma unroll
                for (int j = 0; j < 2; j++) {
                    int n = nt * 8 + 2 * (lane & 3) + j;
                    if (n < N2) {
                        rmax0 = fmaxf(rmax0, acc[mi][nt][j]);
                        rmax1 = fmaxf(rmax1, acc[mi][nt][2 + j]);
                    }
                }
            }
            rmax0 = fmaxf(rmax0, __shfl_xor_sync(0xffffffffu, rmax0, 1));
            rmax0 = fmaxf(rmax0, __shfl_xor_sync(0xffffffffu, rmax0, 2));
            rmax1 = fmaxf(rmax1, __shfl_xor_sync(0xffffffffu, rmax1, 1));
            rmax1 = fmaxf(rmax1, __shfl_xor_sync(0xffffffffu, rmax1, 2));
            if ((lane & 3) == 0) {
                if (ok0) rpart += rmax0;
                if (ok1) rpart += rmax1;
            }
        }
        rpart += __shfl_xor_sync(0xffffffffu, rpart, 16);
        rpart += __shfl_xor_sync(0xffffffffu, rpart, 8);
        rpart += __shfl_xor_sync(0xffffffffu, rpart, 4);
        rpart += __shfl_xor_sync(0xffffffffu, rpart, 2);
        rpart += __shfl_xor_sync(0xffffffffu, rpart, 1);
        if (lane == 0) s_rs[w] = rpart;

        {
            const int r0 = m_base + (lane >> 2);
#pragma unroll
            for (int nt = 0; nt < 10; nt++) {
#pragma unroll
                for (int j = 0; j < 2; j++) {
                    float cm = NEG;
                    for (int mi = 0; mi < nmt; mi++) {
                        const int rr0 = r0 + mi * 16, rr1 = rr0 + 8;
                        if (rr0 < N1) cm = fmaxf(cm, acc[mi][nt][j]);
                        if (rr1 < N1) cm = fmaxf(cm, acc[mi][nt][2 + j]);
                    }
                    cm = fmaxf(cm, __shfl_xor_sync(0xffffffffu, cm, 4));
                    cm = fmaxf(cm, __shfl_xor_sync(0xffffffffu, cm, 8));
                    cm = fmaxf(cm, __shfl_xor_sync(0xffffffffu, cm, 16));
                    if (lane < 4) s_col[w * NPAD + nt * 8 + 2 * lane + j] = cm;
                }
            }
        }
    }

    __syncthreads();   // consumers' s_col/s_rs visible; producers join here

    // final reductions: warp 0 handles h=0 (warps 0-5,12), warp 6 handles h=1 (6-11,13)
    if (w == 0 || w == 6) {
        const int hh = (w == 6);
        const int wbase = hh * 6;
        const int wext = 12 + hh;
        float csum = 0.f;
        for (int n = lane; n < N2; n += 32) {
            float m = ((float*)(smem + SMEM_COL))[wext * NPAD + n];
#pragma unroll
            for (int w2 = 0; w2 < 6; w2++)
                m = fmaxf(m, ((float*)(smem + SMEM_COL))[(wbase + w2) * NPAD + n]);
            csum += m;
        }
        csum += __shfl_xor_sync(0xffffffffu, csum, 16);
        csum += __shfl_xor_sync(0xffffffffu, csum, 8);
        csum += __shfl_xor_sync(0xffffffffu, csum, 4);
        csum += __shfl_xor_sync(0xffffffffu, csum, 2);
        csum += __shfl_xor_sync(0xffffffffu, csum, 1);
        if (lane == 0) {
            float* s_rs = (float*)(smem + SMEM_RS);
            float rs = s_rs[wext];
#pragma unroll
            for (int w2 = 0; w2 < 6; w2++) rs += s_rs[wbase + w2];
            g_i2t[bi * B_ + bt0 + hh] = rs * (1.0f / N1);
            g_t2i[(bt0 + hh) * B_ + bi] = csum * (1.0f / N2);
        }
    }
}

// ---------------------------------------------------------------------------
// Final cross-entropy: 32 warps, one row-task per warp (192 tasks total)
// ---------------------------------------------------------------------------
__global__ void ce_kernel(float* __restrict__ out) {
    __shared__ float spart[32];
    int w = threadIdx.x >> 5, lane = threadIdx.x & 31;
    float acc = 0.f;
    for (int task = w; task < 2 * B_; task += 32) {
        const float* rowp = (task < B_) ? (g_i2t + task * B_) : (g_t2i + (task - B_) * B_);
        int b = (task < B_) ? task : task - B_;
        float v0 = rowp[lane], v1 = rowp[lane + 32], v2 = rowp[lane + 64];
        float mx = fmaxf(v0, fmaxf(v1, v2));
        mx = fmaxf(mx, __shfl_xor_sync(0xffffffffu, mx, 16));
        mx = fmaxf(mx, __shfl_xor_sync(0xffffffffu, mx, 8));
        mx = fmaxf(mx, __shfl_xor_sync(0xffffffffu, mx, 4));
        mx = fmaxf(mx, __shfl_xor_sync(0xffffffffu, mx, 2));
        mx = fmaxf(mx, __shfl_xor_sync(0xffffffffu, mx, 1));
        float s = expf(v0 - mx) + expf(v1 - mx) + expf(v2 - mx);
        s += __shfl_xor_sync(0xffffffffu, s, 16);
        s += __shfl_xor_sync(0xffffffffu, s, 8);
        s += __shfl_xor_sync(0xffffffffu, s, 4);
        s += __shfl_xor_sync(0xffffffffu, s, 2);
        s += __shfl_xor_sync(0xffffffffu, s, 1);
        if (lane == 0) acc += mx + logf(s) - rowp[b];
    }
    if (lane == 0) spart[w] = acc;
    __syncthreads();
    if (w == 0) {
        float v = spart[lane];
        v += __shfl_xor_sync(0xffffffffu, v, 16);
        v += __shfl_xor_sync(0xffffffffu, v, 8);
        v += __shfl_xor_sync(0xffffffffu, v, 4);
        v += __shfl_xor_sync(0xffffffffu, v, 2);
        v += __shfl_xor_sync(0xffffffffu, v, 1);
        if (lane == 0) out[0] = 0.5f * v * (1.0f / B_);
    }
}

// ---------------------------------------------------------------------------
extern "C" void kernel_launch(void* const* d_in, const int* in_sizes, int n_in,
                              void* d_out, int out_size) {
    const float* img = (const float*)d_in[0];   // [96, 196, 512] fp32
    const float* txt = (const float*)d_in[1];   // [96, 77, 512] fp32
    float* out = (float*)d_out;

    cudaFuncSetAttribute(gemm_pair_kernel,
                         cudaFuncAttributeMaxDynamicSharedMemorySize, SMEM_TOTAL);

    {
        int tot = B_ * MPAD * (DIM / 2);
        conv_img_kernel<<<(tot + 255) / 256, 256>>>(img);
    }
    {
        int tot = B_ * NPAD * (DIM / 2);
        conv_txt_kernel<<<(tot + 255) / 256, 256>>>(txt);
    }
    gemm_pair_kernel<<<dim3(B_ / Gg, B_), NTHREADS, SMEM_TOTAL>>>();
    ce_kernel<<<1, 1024>>>(out);
}